// round 4
// baseline (speedup 1.0000x reference)
#include <cuda_runtime.h>
#include <cuda_fp16.h>
#include <cstdint>

// Problem shape (fixed): T=1024, B=128, F=512
//   xs[t,b,g] = sum_f spikes[t,b,f] * W[g,f]   -> GEMM  M=131072, N=512, K=512
//   then sequential LIF scan over t, output final (z, z, v, i), each [128,512].

#define Tn 1024
#define Bn 128
#define Fn 512
#define Mrows (Tn * Bn)          // 131072
#define NEURONS (Bn * Fn)        // 65536
#define EPS 1e-4f                // margin threshold for exact-recompute flagging

// scratch (module-scope device arrays: allowed, not runtime allocs)
__device__ float g_xs[(size_t)Mrows * Fn];                          // 268 MB
__device__ __align__(16) __half g_A1[(size_t)Mrows * Fn];           // 134 MB
__device__ __align__(16) __half g_A2[(size_t)Mrows * Fn];           // 134 MB
__device__ __align__(16) __half g_W1[Fn * Fn];
__device__ __align__(16) __half g_W2[Fn * Fn];
__device__ int g_cnt[Bn];
__device__ int g_list[Bn * Fn];

// ---------------------------------------------------------------------------
__device__ __forceinline__ uint32_t smem_to_u32(const void* p) {
    uint32_t a;
    asm("{ .reg .u64 t; cvta.to.shared.u64 t, %1; cvt.u32.u64 %0, t; }"
        : "=r"(a) : "l"(p));
    return a;
}

#define CP_ASYNC16(dst, src) \
    asm volatile("cp.async.cg.shared.global [%0], [%1], 16;" \
        :: "r"(dst), "l"(src) : "memory")
#define CP_COMMIT() asm volatile("cp.async.commit_group;" ::: "memory")
#define CP_WAIT1()  asm volatile("cp.async.wait_group 1;" ::: "memory")

#define LDSM4(r0, r1, r2, r3, addr) \
    asm volatile("ldmatrix.sync.aligned.m8n8.x4.shared.b16 {%0,%1,%2,%3}, [%4];" \
        : "=r"(r0), "=r"(r1), "=r"(r2), "=r"(r3) : "r"(addr))

#define MMA16816(d, a, b0, b1) \
    asm volatile("mma.sync.aligned.m16n8k16.row.col.f32.f16.f16.f32 " \
        "{%0,%1,%2,%3}, {%4,%5,%6,%7}, {%8,%9}, {%0,%1,%2,%3};" \
        : "+f"((d)[0]), "+f"((d)[1]), "+f"((d)[2]), "+f"((d)[3]) \
        : "r"((a)[0]), "r"((a)[1]), "r"((a)[2]), "r"((a)[3]), \
          "r"(b0), "r"(b1))

// fp16 2-way split: x = h1 + h2 + O(2^-23 x)
__device__ __forceinline__ void split2(float x, __half& h1, __half& h2) {
    h1 = __float2half_rn(x);
    h2 = __float2half_rn(x - __half2float(h1));
}

// ---------------------------------------------------------------------------
// split kernels
// ---------------------------------------------------------------------------
__global__ void wsplit_kernel(const float* __restrict__ W) {
    int i = (blockIdx.x * blockDim.x + threadIdx.x) * 4;
    float4 x = *(const float4*)(W + i);
    __half a1, a2, b1, b2, c1, c2, d1, d2;
    split2(x.x, a1, a2); split2(x.y, b1, b2);
    split2(x.z, c1, c2); split2(x.w, d1, d2);
    __half2 p1a = __halves2half2(a1, b1), p1b = __halves2half2(c1, d1);
    __half2 p2a = __halves2half2(a2, b2), p2b = __halves2half2(c2, d2);
    *(uint2*)(g_W1 + i) = make_uint2(*(uint32_t*)&p1a, *(uint32_t*)&p1b);
    *(uint2*)(g_W2 + i) = make_uint2(*(uint32_t*)&p2a, *(uint32_t*)&p2b);
}

__global__ __launch_bounds__(256)
void asplit_kernel(const float* __restrict__ A) {
    size_t i = ((size_t)blockIdx.x * blockDim.x + threadIdx.x) * 4;
    float4 x = *(const float4*)(A + i);
    __half a1, a2, b1, b2, c1, c2, d1, d2;
    split2(x.x, a1, a2); split2(x.y, b1, b2);
    split2(x.z, c1, c2); split2(x.w, d1, d2);
    __half2 p1a = __halves2half2(a1, b1), p1b = __halves2half2(c1, d1);
    __half2 p2a = __halves2half2(a2, b2), p2b = __halves2half2(c2, d2);
    *(uint2*)(g_A1 + i) = make_uint2(*(uint32_t*)&p1a, *(uint32_t*)&p1b);
    *(uint2*)(g_A2 + i) = make_uint2(*(uint32_t*)&p2a, *(uint32_t*)&p2b);
}

__global__ void zero_cnt_kernel() { g_cnt[threadIdx.x] = 0; }

// ---------------------------------------------------------------------------
// HMMA GEMM: C[M,512] = A[M,512] * W^T, ~fp32-accurate via fp16 x 3 products.
// CTA 128x128, BK=32, 256 threads = 8 warps (2 along M x 4 along N),
// warp tile 64x32. SMEM rows padded to 80B -> conflict-free ldmatrix.
// ---------------------------------------------------------------------------
#define PLA   10240                // one plane: 128 rows * 80B
#define STAGE (4 * PLA)            // A1,A2,B1,B2 planes
#define DSMEM (2 * STAGE)          // 81920 B double buffered

__global__ __launch_bounds__(256)
void gemm_hmma_kernel()
{
    extern __shared__ char sm[];
    const uint32_t sb = smem_to_u32(sm);

    const int tid  = threadIdx.x;
    const int lane = tid & 31;
    const int wid  = tid >> 5;
    const int warp_m = wid & 1;         // 0..1 -> 64-row half
    const int warp_n = wid >> 1;        // 0..3 -> 32-col slice
    const int row0 = blockIdx.y * 128;
    const int col0 = blockIdx.x * 128;

    const __half* gA[2] = { g_A1, g_A2 };
    const __half* gB[2] = { g_W1, g_W2 };

    const int grp = lane >> 3, lr = lane & 7;
    const uint32_t aLane = (uint32_t)((warp_m * 64 + (grp & 1) * 8 + lr) * 80
                                      + ((grp >> 1) * 8) * 2);
    const uint32_t bLane = (uint32_t)((warp_n * 32 + (grp >> 1) * 8 + lr) * 80
                                      + ((grp & 1) * 8) * 2);

    float acc[4][4][4];
#pragma unroll
    for (int mt = 0; mt < 4; ++mt)
#pragma unroll
        for (int nn = 0; nn < 4; ++nn)
#pragma unroll
            for (int e = 0; e < 4; ++e) acc[mt][nn][e] = 0.0f;

    auto issue = [&](int it, int buf) {
        const uint32_t dst0 = sb + (uint32_t)buf * STAGE;
        const int kt = it * 32;
#pragma unroll
        for (int q = 0; q < 8; ++q) {
            int id  = q * 256 + tid;
            int isB = id >> 10;
            int id2 = id & 1023;
            int p = id2 >> 9, r = (id2 >> 2) & 127, c = id2 & 3;
            const __half* src = (isB ? gB[p] + (size_t)(col0 + r) * Fn
                                     : gA[p] + (size_t)(row0 + r) * Fn) + kt + c * 8;
            uint32_t dst = dst0 + (uint32_t)(isB * 2 * PLA + p * PLA + r * 80 + c * 16);
            CP_ASYNC16(dst, src);
        }
    };

    issue(0, 0); CP_COMMIT();
    issue(1, 1); CP_COMMIT();

    for (int it = 0; it < 16; ++it) {
        const int buf = it & 1;
        CP_WAIT1();
        __syncthreads();

        const uint32_t base = sb + (uint32_t)buf * STAGE;
#pragma unroll
        for (int ks = 0; ks < 2; ++ks) {
            uint32_t a[2][4][4];
            uint32_t b[2][2][4];
#pragma unroll
            for (int pl = 0; pl < 2; ++pl) {
#pragma unroll
                for (int mt = 0; mt < 4; ++mt) {
                    uint32_t ad = base + (uint32_t)(pl * PLA) + aLane
                                + (uint32_t)(mt * 16 * 80 + ks * 32);
                    LDSM4(a[pl][mt][0], a[pl][mt][1], a[pl][mt][2], a[pl][mt][3], ad);
                }
#pragma unroll
                for (int j = 0; j < 2; ++j) {
                    uint32_t bd = base + (uint32_t)(2 * PLA + pl * PLA) + bLane
                                + (uint32_t)(j * 16 * 80 + ks * 32);
                    LDSM4(b[pl][j][0], b[pl][j][1], b[pl][j][2], b[pl][j][3], bd);
                }
            }
#pragma unroll
            for (int mt = 0; mt < 4; ++mt)
#pragma unroll
                for (int j = 0; j < 2; ++j)
#pragma unroll
                    for (int h = 0; h < 2; ++h) {
                        const int nn = j * 2 + h;
                        MMA16816(acc[mt][nn], a[0][mt], b[0][j][h*2], b[0][j][h*2+1]);
                        MMA16816(acc[mt][nn], a[0][mt], b[1][j][h*2], b[1][j][h*2+1]);
                        MMA16816(acc[mt][nn], a[1][mt], b[0][j][h*2], b[0][j][h*2+1]);
                    }
        }
        __syncthreads();
        if (it + 2 < 16) issue(it + 2, buf);
        CP_COMMIT();
    }

    const int tr = lane >> 2;
    const int tc = (lane & 3) * 2;
    const int rbase = row0 + warp_m * 64;
    const int cbase = col0 + warp_n * 32;
#pragma unroll
    for (int mt = 0; mt < 4; ++mt)
#pragma unroll
        for (int nn = 0; nn < 4; ++nn) {
            float* p0 = g_xs + (size_t)(rbase + mt * 16 + tr) * Fn + cbase + nn * 8 + tc;
            *(float2*)(p0)            = make_float2(acc[mt][nn][0], acc[mt][nn][1]);
            *(float2*)(p0 + 8 * Fn)   = make_float2(acc[mt][nn][2], acc[mt][nn][3]);
        }
}

// ---------------------------------------------------------------------------
// LIF scan pass 1: also tracks min |v_dec - 1| margin; flags risky neurons.
// If margin >= EPS, all z decisions provably match the exact fp32 scan
// (|x_hat - x_ref| <= ~3e-6  =>  |v_dec deviation| <= 1.5e-5 << EPS).
// ---------------------------------------------------------------------------
__global__ __launch_bounds__(256)
void lif_scan_kernel(float* __restrict__ out)
{
    const int n = blockIdx.x * blockDim.x + threadIdx.x;   // 0..65535
    const float* xp = g_xs + n;

    float v = 0.0f, cur = 0.0f, z = 0.0f;
    float margin = 1e30f;

    float xb[8];
#pragma unroll
    for (int j = 0; j < 8; j++) xb[j] = __ldg(xp + (size_t)j * NEURONS);

    for (int t0 = 0; t0 < Tn; t0 += 8) {
        float xn[8] = {0.f, 0.f, 0.f, 0.f, 0.f, 0.f, 0.f, 0.f};
        if (t0 + 8 < Tn) {
#pragma unroll
            for (int j = 0; j < 8; j++)
                xn[j] = __ldg(xp + (size_t)(t0 + 8 + j) * NEURONS);
        }
#pragma unroll
        for (int j = 0; j < 8; j++) {
            float vd = fmaf(0.1f, cur - v, v);
            float id = fmaf(-0.2f, cur, cur);
            margin = fminf(margin, fabsf(vd - 1.0f));
            bool  sp = (vd - 1.0f) > 0.0f;
            z   = sp ? 1.0f : 0.0f;
            v   = sp ? 0.0f : vd;
            cur = id + xb[j];
        }
#pragma unroll
        for (int j = 0; j < 8; j++) xb[j] = xn[j];
    }

    out[n]               = z;
    out[NEURONS + n]     = z;
    out[2 * NEURONS + n] = v;
    out[3 * NEURONS + n] = cur;

    if (margin < EPS) {
        int b = n >> 9;
        int idx = atomicAdd(&g_cnt[b], 1);
        g_list[(b << 9) + idx] = n & 511;
    }
}

// ---------------------------------------------------------------------------
// Fixup pass A: recompute x EXACTLY (ascending-f fp32 fmaf, matches reference
// bit-for-bit per R1) for flagged neurons; overwrite g_xs columns.
// One CTA per batch row b; smem spike tile 64t x 512f (row stride 524 floats).
// ---------------------------------------------------------------------------
#define FIX_SMEM (64 * 524 * 4)

__global__ __launch_bounds__(256)
void fixup_x_kernel(const float* __restrict__ spikes, const float* __restrict__ W)
{
    const int b = blockIdx.x;
    const int nf = g_cnt[b];
    if (nf == 0) return;

    extern __shared__ float s_spk[];          // [64][524]
    const int tid = threadIdx.x;
    const int tl  = tid & 63;                 // local t
    const int gl  = tid >> 6;                 // 0..3

    for (int t0 = 0; t0 < Tn; t0 += 64) {
        // cooperative load: 64 rows x 512 floats (coalesced float4)
        for (int i = tid; i < 64 * 128; i += 256) {
            int r  = i >> 7;
            int c4 = (i & 127) << 2;
            float4 v = *(const float4*)(spikes + (size_t)(t0 + r) * NEURONS
                                        + (size_t)b * Fn + c4);
            *(float4*)(s_spk + r * 524 + c4) = v;
        }
        __syncthreads();

        for (int gb = 0; gb < nf; gb += 8) {
            const bool hA = (gb + gl)     < nf;
            const bool hB = (gb + gl + 4) < nf;
            const int gA = hA ? g_list[(b << 9) + gb + gl]     : 0;
            const int gB = hB ? g_list[(b << 9) + gb + gl + 4] : 0;
            const float* WA = W + (size_t)gA * Fn;
            const float* WB = W + (size_t)gB * Fn;
            const float* sp = s_spk + tl * 524;

            float xa = 0.0f, xb2 = 0.0f;
#pragma unroll 8
            for (int f = 0; f < Fn; f += 4) {
                float4 s  = *(const float4*)(sp + f);
                float4 wa = *(const float4*)(WA + f);
                float4 wb = *(const float4*)(WB + f);
                xa  = fmaf(s.x, wa.x, xa);  xa  = fmaf(s.y, wa.y, xa);
                xa  = fmaf(s.z, wa.z, xa);  xa  = fmaf(s.w, wa.w, xa);
                xb2 = fmaf(s.x, wb.x, xb2); xb2 = fmaf(s.y, wb.y, xb2);
                xb2 = fmaf(s.z, wb.z, xb2); xb2 = fmaf(s.w, wb.w, xb2);
            }
            size_t rowoff = (size_t)(t0 + tl) * NEURONS + (size_t)b * Fn;
            if (hA) g_xs[rowoff + gA] = xa;
            if (hB) g_xs[rowoff + gB] = xb2;
        }
        __syncthreads();
    }
}

// ---------------------------------------------------------------------------
// Fixup pass B: exact rescan of flagged neurons from corrected g_xs.
// ---------------------------------------------------------------------------
__global__ __launch_bounds__(512)
void fixup_scan_kernel(float* __restrict__ out)
{
    const int b = blockIdx.x;
    const int tid = threadIdx.x;
    if (tid >= g_cnt[b]) return;
    const int g = g_list[(b << 9) + tid];
    const int n = (b << 9) + g;
    const float* xp = g_xs + n;

    float v = 0.0f, cur = 0.0f, z = 0.0f;
    float xb[4];
#pragma unroll
    for (int j = 0; j < 4; j++) xb[j] = __ldg(xp + (size_t)j * NEURONS);

    for (int t0 = 0; t0 < Tn; t0 += 4) {
        float xn[4] = {0.f, 0.f, 0.f, 0.f};
        if (t0 + 4 < Tn) {
#pragma unroll
            for (int j = 0; j < 4; j++)
                xn[j] = __ldg(xp + (size_t)(t0 + 4 + j) * NEURONS);
        }
#pragma unroll
        for (int j = 0; j < 4; j++) {
            float vd = fmaf(0.1f, cur - v, v);
            float id = fmaf(-0.2f, cur, cur);
            bool  sp = (vd - 1.0f) > 0.0f;
            z   = sp ? 1.0f : 0.0f;
            v   = sp ? 0.0f : vd;
            cur = id + xb[j];
        }
#pragma unroll
        for (int j = 0; j < 4; j++) xb[j] = xn[j];
    }

    out[n]               = z;
    out[NEURONS + n]     = z;
    out[2 * NEURONS + n] = v;
    out[3 * NEURONS + n] = cur;
}

// ---------------------------------------------------------------------------
extern "C" void kernel_launch(void* const* d_in, const int* in_sizes, int n_in,
                              void* d_out, int out_size)
{
    const float* spikes = (const float*)d_in[0];   // [1024,128,512]
    const float* W      = (const float*)d_in[1];   // [512,512]
    float* out          = (float*)d_out;           // 4 * 65536 floats

    cudaFuncSetAttribute(gemm_hmma_kernel,
                         cudaFuncAttributeMaxDynamicSharedMemorySize, DSMEM);
    cudaFuncSetAttribute(fixup_x_kernel,
                         cudaFuncAttributeMaxDynamicSharedMemorySize, FIX_SMEM);

    wsplit_kernel<<<Fn * Fn / 1024, 256>>>(W);
    asplit_kernel<<<(int)((size_t)Mrows * Fn / 1024), 256>>>(spikes);
    dim3 grid(Fn / 128, Mrows / 128);              // (4, 1024)
    gemm_hmma_kernel<<<grid, 256, DSMEM>>>();
    zero_cnt_kernel<<<1, Bn>>>();
    lif_scan_kernel<<<NEURONS / 256, 256>>>(out);
    fixup_x_kernel<<<Bn, 256, FIX_SMEM>>>(spikes, W);
    fixup_scan_kernel<<<Bn, 512>>>(out);
}

// round 8
// speedup vs baseline: 1.6586x; 1.6586x over previous
#include <cuda_runtime.h>
#include <cstdint>

// Problem shape (fixed): T=1024, B=128, F=512
//   xs[t,b,g] = sum_f spikes[t,b,f] * W[g,f]   -> GEMM  M=131072, N=512, K=512
//   then sequential LIF scan over t, output final (z, z, v, i), each [128,512].

#define Tn 1024
#define Bn 128
#define Fn 512
#define Mrows (Tn * Bn)          // 131072
#define NEURONS (Bn * Fn)        // 65536

// 268 MB scratch for xs (module-scope device array: allowed, not runtime alloc)
__device__ float g_xs[(size_t)Mrows * Fn];

// ---------------------------------------------------------------------------
// SGEMM:  C[M,512] = A[M,512] * W[512,512]^T   (both K-major, K=512)
// CTA tile 128x128, BK=32, 256 threads, 8x8 microtile, double-buffered smem
// (one __syncthreads per BK=32 chunk), 2 CTAs/SM.
// ---------------------------------------------------------------------------
__global__ __launch_bounds__(256, 2)
void sgemm_nt_kernel(const float* __restrict__ A,
                     const float* __restrict__ W)
{
    // [buf][k][row] transposed tiles
    __shared__ float As[2][32][128];
    __shared__ float Bs[2][32][128];

    const int tid  = threadIdx.x;
    const int tx   = tid & 15;          // output cols tx*8..tx*8+7
    const int ty   = tid >> 4;          // output rows ty*8..ty*8+7
    const int row0 = blockIdx.y * 128;
    const int col0 = blockIdx.x * 128;

    // loaders: 4 threads per row, contiguous 64B chunks (full sectors)
    const int lrow = tid >> 2;          // 0..63
    const int lk   = (tid & 3) * 4;     // k offset 0,4,8,12 (+16 for j=1)

    const float* Ap = A + (size_t)(row0 + lrow) * Fn + lk;
    const float* Wp = W + (size_t)(col0 + lrow) * Fn + lk;

    float4 ra[4], rw[4];                // staging: rows {lrow, lrow+64} x k {lk, lk+16}
#pragma unroll
    for (int j = 0; j < 2; ++j) {
        ra[j]     = *(const float4*)(Ap + j * 16);
        ra[j + 2] = *(const float4*)(Ap + j * 16 + 64 * Fn);
        rw[j]     = *(const float4*)(Wp + j * 16);
        rw[j + 2] = *(const float4*)(Wp + j * 16 + 64 * Fn);
    }

    float acc[8][8];
#pragma unroll
    for (int i = 0; i < 8; i++)
#pragma unroll
        for (int j = 0; j < 8; j++) acc[i][j] = 0.0f;

    // store staged regs into buffer b (transposed [k][row])
    auto stage_sts = [&](int b) {
#pragma unroll
        for (int j = 0; j < 2; ++j) {
            int kk = lk + j * 16;
            As[b][kk + 0][lrow]      = ra[j].x;
            As[b][kk + 1][lrow]      = ra[j].y;
            As[b][kk + 2][lrow]      = ra[j].z;
            As[b][kk + 3][lrow]      = ra[j].w;
            As[b][kk + 0][lrow + 64] = ra[j + 2].x;
            As[b][kk + 1][lrow + 64] = ra[j + 2].y;
            As[b][kk + 2][lrow + 64] = ra[j + 2].z;
            As[b][kk + 3][lrow + 64] = ra[j + 2].w;
            Bs[b][kk + 0][lrow]      = rw[j].x;
            Bs[b][kk + 1][lrow]      = rw[j].y;
            Bs[b][kk + 2][lrow]      = rw[j].z;
            Bs[b][kk + 3][lrow]      = rw[j].w;
            Bs[b][kk + 0][lrow + 64] = rw[j + 2].x;
            Bs[b][kk + 1][lrow + 64] = rw[j + 2].y;
            Bs[b][kk + 2][lrow + 64] = rw[j + 2].z;
            Bs[b][kk + 3][lrow + 64] = rw[j + 2].w;
        }
    };

    stage_sts(0);
    __syncthreads();

    for (int it = 0; it < 16; ++it) {
        const int b = it & 1;

        // prefetch next tile into regs (overlaps with compute below)
        if (it + 1 < 16) {
            const int kt = (it + 1) * 32;
#pragma unroll
            for (int j = 0; j < 2; ++j) {
                ra[j]     = *(const float4*)(Ap + kt + j * 16);
                ra[j + 2] = *(const float4*)(Ap + kt + j * 16 + 64 * Fn);
                rw[j]     = *(const float4*)(Wp + kt + j * 16);
                rw[j + 2] = *(const float4*)(Wp + kt + j * 16 + 64 * Fn);
            }
        }

#pragma unroll
        for (int k = 0; k < 32; k++) {
            float4 a0 = *(const float4*)(&As[b][k][ty * 8]);
            float4 a1 = *(const float4*)(&As[b][k][ty * 8 + 4]);
            float4 b0 = *(const float4*)(&Bs[b][k][tx * 8]);
            float4 b1 = *(const float4*)(&Bs[b][k][tx * 8 + 4]);
            float av[8] = {a0.x, a0.y, a0.z, a0.w, a1.x, a1.y, a1.z, a1.w};
            float bv[8] = {b0.x, b0.y, b0.z, b0.w, b1.x, b1.y, b1.z, b1.w};
#pragma unroll
            for (int i = 0; i < 8; i++)
#pragma unroll
                for (int j = 0; j < 8; j++)
                    acc[i][j] = fmaf(av[i], bv[j], acc[i][j]);
        }

        // store next tile into the other buffer (safe: nobody reads it now)
        if (it + 1 < 16) stage_sts(b ^ 1);
        __syncthreads();
    }

    // write C (g_xs), coalesced float4
#pragma unroll
    for (int i = 0; i < 8; i++) {
        float* cp = g_xs + (size_t)(row0 + ty * 8 + i) * Fn + col0 + tx * 8;
        float4 c0 = {acc[i][0], acc[i][1], acc[i][2], acc[i][3]};
        float4 c1 = {acc[i][4], acc[i][5], acc[i][6], acc[i][7]};
        *(float4*)(cp)     = c0;
        *(float4*)(cp + 4) = c1;
    }
}

// ---------------------------------------------------------------------------
// LIF scan: one thread per neuron, sequential over T with 16-deep x prefetch.
// Matches reference arithmetic exactly:
//   v_dec = v + 0.1*((0 - v) + i); i_dec = i + (-0.2)*i
//   z = (v_dec - 1) > 0 ; v = z ? 0 : v_dec ; i = i_dec + x_t
// ---------------------------------------------------------------------------
__global__ __launch_bounds__(256)
void lif_scan_kernel(float* __restrict__ out)
{
    const int n = blockIdx.x * blockDim.x + threadIdx.x;   // 0..65535
    const float* xp = g_xs + n;

    float v = 0.0f, cur = 0.0f, z = 0.0f;

    float xb[16];
#pragma unroll
    for (int j = 0; j < 16; j++) xb[j] = __ldg(xp + (size_t)j * NEURONS);

    for (int t0 = 0; t0 < Tn; t0 += 16) {
        float xn[16];
#pragma unroll
        for (int j = 0; j < 16; j++) xn[j] = 0.0f;
        if (t0 + 16 < Tn) {
#pragma unroll
            for (int j = 0; j < 16; j++)
                xn[j] = __ldg(xp + (size_t)(t0 + 16 + j) * NEURONS);
        }
#pragma unroll
        for (int j = 0; j < 16; j++) {
            float vd = fmaf(0.1f, cur - v, v);       // v + 0.1*((0-v)+i)
            float id = fmaf(-0.2f, cur, cur);        // i + (-0.2)*i
            bool  sp = (vd - 1.0f) > 0.0f;
            z   = sp ? 1.0f : 0.0f;
            v   = sp ? 0.0f : vd;
            cur = id + xb[j];
        }
#pragma unroll
        for (int j = 0; j < 16; j++) xb[j] = xn[j];
    }

    out[n]               = z;   // z_final
    out[NEURONS + n]     = z;   // z_final (returned twice)
    out[2 * NEURONS + n] = v;   // v_final
    out[3 * NEURONS + n] = cur; // i_final
}

// ---------------------------------------------------------------------------
extern "C" void kernel_launch(void* const* d_in, const int* in_sizes, int n_in,
                              void* d_out, int out_size)
{
    const float* spikes = (const float*)d_in[0];   // [1024,128,512]
    const float* W      = (const float*)d_in[1];   // [512,512]
    float* out          = (float*)d_out;           // 4 * 65536 floats

    dim3 grid(Fn / 128, Mrows / 128);              // (4, 1024)
    sgemm_nt_kernel<<<grid, 256>>>(spikes, W);
    lif_scan_kernel<<<NEURONS / 256, 256>>>(out);
}

// round 11
// speedup vs baseline: 1.6917x; 1.0199x over previous
#include <cuda_runtime.h>
#include <cstdint>

// Problem shape (fixed): T=1024, B=128, F=512
//   xs[t,b,g] = sum_f spikes[t,b,f] * W[g,f]   -> GEMM  M=131072, N=512, K=512
//   then sequential LIF scan over t, output final (z, z, v, i), each [128,512].

#define Tn 1024
#define Bn 128
#define Fn 512
#define Mrows (Tn * Bn)          // 131072
#define NEURONS (Bn * Fn)        // 65536

// 268 MB scratch for xs (module-scope device array: allowed, not runtime alloc)
__device__ float g_xs[(size_t)Mrows * Fn];

// packed dual fp32 FMA: d.lo += a.lo*b.lo ; d.hi += a.hi*b.hi (IEEE fp32 each)
__device__ __forceinline__ void ffma2(uint64_t& d, uint64_t a, uint64_t b) {
    asm("fma.rn.f32x2 %0, %1, %2, %0;" : "+l"(d) : "l"(a), "l"(b));
}
__device__ __forceinline__ uint64_t dup2(float x) {
    uint64_t r;
    asm("mov.b64 %0, {%1, %1};" : "=l"(r) : "f"(x));
    return r;
}

// ---------------------------------------------------------------------------
// SGEMM:  C[M,512] = A[M,512] * W[512,512]^T   (both K-major, K=512)
// CTA tile 128x128, BK=16, 256 threads, 8x8 microtile computed as 8x4 f32x2
// packed FMAs (32 FFMA2 per k-step instead of 64 FFMA).
// ---------------------------------------------------------------------------
__global__ __launch_bounds__(256, 2)
void sgemm_nt_kernel(const float* __restrict__ A,
                     const float* __restrict__ W)
{
    __shared__ float As[16][128];
    __shared__ float Bs[16][128];

    const int tid  = threadIdx.x;
    const int tx   = tid & 15;          // output cols tx*8..tx*8+7
    const int ty   = tid >> 4;          // output rows ty*8..ty*8+7
    const int row0 = blockIdx.y * 128;
    const int col0 = blockIdx.x * 128;

    // loading layout: 512 float4 per 128x16 tile, 2 per thread
    const int lrow = tid >> 2;          // 0..63
    const int lk4  = (tid & 3) * 4;     // k offset 0,4,8,12

    const float* Ap = A + (size_t)(row0 + lrow) * Fn + lk4;
    const float* Wp = W + (size_t)(col0 + lrow) * Fn + lk4;

    float4 ra0 = *(const float4*)(Ap);
    float4 ra1 = *(const float4*)(Ap + 64 * Fn);
    float4 rw0 = *(const float4*)(Wp);
    float4 rw1 = *(const float4*)(Wp + 64 * Fn);

    // accumulators: [row i][col-pair jp] -> packed (c2jp, c2jp+1)
    uint64_t acc[8][4];
#pragma unroll
    for (int i = 0; i < 8; i++)
#pragma unroll
        for (int j = 0; j < 4; j++) acc[i][j] = 0ull;

    for (int kt = 0; kt < Fn; kt += 16) {
        // stage registers -> smem (transposed to [k][row])
        As[lk4 + 0][lrow]      = ra0.x;
        As[lk4 + 1][lrow]      = ra0.y;
        As[lk4 + 2][lrow]      = ra0.z;
        As[lk4 + 3][lrow]      = ra0.w;
        As[lk4 + 0][lrow + 64] = ra1.x;
        As[lk4 + 1][lrow + 64] = ra1.y;
        As[lk4 + 2][lrow + 64] = ra1.z;
        As[lk4 + 3][lrow + 64] = ra1.w;

        Bs[lk4 + 0][lrow]      = rw0.x;
        Bs[lk4 + 1][lrow]      = rw0.y;
        Bs[lk4 + 2][lrow]      = rw0.z;
        Bs[lk4 + 3][lrow]      = rw0.w;
        Bs[lk4 + 0][lrow + 64] = rw1.x;
        Bs[lk4 + 1][lrow + 64] = rw1.y;
        Bs[lk4 + 2][lrow + 64] = rw1.z;
        Bs[lk4 + 3][lrow + 64] = rw1.w;
        __syncthreads();

        // prefetch next k-tile while computing this one
        if (kt + 16 < Fn) {
            ra0 = *(const float4*)(Ap + kt + 16);
            ra1 = *(const float4*)(Ap + kt + 16 + 64 * Fn);
            rw0 = *(const float4*)(Wp + kt + 16);
            rw1 = *(const float4*)(Wp + kt + 16 + 64 * Fn);
        }

#pragma unroll
        for (int k = 0; k < 16; k++) {
            float4 a0 = *(const float4*)(&As[k][ty * 8]);
            float4 a1 = *(const float4*)(&As[k][ty * 8 + 4]);
            uint64_t bv[4];
#pragma unroll
            for (int jp = 0; jp < 4; jp++)
                bv[jp] = *(const uint64_t*)(&Bs[k][tx * 8 + jp * 2]);
            uint64_t ad[8] = { dup2(a0.x), dup2(a0.y), dup2(a0.z), dup2(a0.w),
                               dup2(a1.x), dup2(a1.y), dup2(a1.z), dup2(a1.w) };
#pragma unroll
            for (int i = 0; i < 8; i++)
#pragma unroll
                for (int jp = 0; jp < 4; jp++)
                    ffma2(acc[i][jp], ad[i], bv[jp]);
        }
        __syncthreads();
    }

    // write C (g_xs): each u64 holds two adjacent columns
#pragma unroll
    for (int i = 0; i < 8; i++) {
        float* cp = g_xs + (size_t)(row0 + ty * 8 + i) * Fn + col0 + tx * 8;
        ulonglong2 v0 = { acc[i][0], acc[i][1] };
        ulonglong2 v1 = { acc[i][2], acc[i][3] };
        *(ulonglong2*)(cp)     = v0;
        *(ulonglong2*)(cp + 4) = v1;
    }
}

// ---------------------------------------------------------------------------
// LIF scan: one thread per neuron, sequential over T with 8-deep x prefetch.
// Matches reference arithmetic exactly:
//   v_dec = v + 0.1*((0 - v) + i); i_dec = i + (-0.2)*i
//   z = (v_dec - 1) > 0 ; v = z ? 0 : v_dec ; i = i_dec + x_t
// ---------------------------------------------------------------------------
__global__ __launch_bounds__(256)
void lif_scan_kernel(float* __restrict__ out)
{
    const int n = blockIdx.x * blockDim.x + threadIdx.x;   // 0..65535
    const float* xp = g_xs + n;

    float v = 0.0f, cur = 0.0f, z = 0.0f;

    float xb[8];
#pragma unroll
    for (int j = 0; j < 8; j++) xb[j] = __ldg(xp + (size_t)j * NEURONS);

    for (int t0 = 0; t0 < Tn; t0 += 8) {
        float xn[8] = {0.f, 0.f, 0.f, 0.f, 0.f, 0.f, 0.f, 0.f};
        if (t0 + 8 < Tn) {
#pragma unroll
            for (int j = 0; j < 8; j++)
                xn[j] = __ldg(xp + (size_t)(t0 + 8 + j) * NEURONS);
        }
#pragma unroll
        for (int j = 0; j < 8; j++) {
            float vd = fmaf(0.1f, cur - v, v);       // v + 0.1*((0-v)+i)
            float id = fmaf(-0.2f, cur, cur);        // i + (-0.2)*i
            bool  sp = (vd - 1.0f) > 0.0f;
            z   = sp ? 1.0f : 0.0f;
            v   = sp ? 0.0f : vd;
            cur = id + xb[j];
        }
#pragma unroll
        for (int j = 0; j < 8; j++) xb[j] = xn[j];
    }

    out[n]               = z;   // z_final
    out[NEURONS + n]     = z;   // z_final (returned twice)
    out[2 * NEURONS + n] = v;   // v_final
    out[3 * NEURONS + n] = cur; // i_final
}

// ---------------------------------------------------------------------------
extern "C" void kernel_launch(void* const* d_in, const int* in_sizes, int n_in,
                              void* d_out, int out_size)
{
    const float* spikes = (const float*)d_in[0];   // [1024,128,512]
    const float* W      = (const float*)d_in[1];   // [512,512]
    float* out          = (float*)d_out;           // 4 * 65536 floats

    dim3 grid(Fn / 128, Mrows / 128);              // (4, 1024)
    sgemm_nt_kernel<<<grid, 256>>>(spikes, W);
    lif_scan_kernel<<<NEURONS / 256, 256>>>(out);
}

// round 14
// speedup vs baseline: 2.2518x; 1.3311x over previous
#include <cuda_runtime.h>
#include <cstdint>

// Problem shape (fixed): T=1024, B=128, F=512
//   xs[t,b,g] = sum_f spikes[t,b,f] * W[g,f]   -> GEMM  M=131072, N=512, K=512
//   then sequential LIF scan over t, output final (z, z, v, i), each [128,512].

#define Tn 1024
#define Bn 128
#define Fn 512
#define Mrows (Tn * Bn)          // 131072
#define NEURONS (Bn * Fn)        // 65536

// module-scope device scratch (allowed; not a runtime alloc)
__device__ float g_xs[(size_t)Mrows * Fn];     // 268 MB
__device__ float g_Wt[Fn * Fn];                // W transposed: Wt[k][g]

// packed dual fp32 FMA: d.lo += a.lo*b.lo ; d.hi += a.hi*b.hi (IEEE fp32 each)
__device__ __forceinline__ void ffma2(uint64_t& d, uint64_t a, uint64_t b) {
    asm("fma.rn.f32x2 %0, %1, %2, %0;" : "+l"(d) : "l"(a), "l"(b));
}
__device__ __forceinline__ uint64_t dup2(float x) {
    uint64_t r;
    asm("mov.b64 %0, {%1, %1};" : "=l"(r) : "f"(x));
    return r;
}
__device__ __forceinline__ uint32_t smem_to_u32(const void* p) {
    uint32_t a;
    asm("{ .reg .u64 t; cvta.to.shared.u64 t, %1; cvt.u32.u64 %0, t; }"
        : "=r"(a) : "l"(p));
    return a;
}
#define CP_ASYNC16(dst, src) \
    asm volatile("cp.async.cg.shared.global [%0], [%1], 16;" \
        :: "r"(dst), "l"(src) : "memory")
#define CP_COMMIT() asm volatile("cp.async.commit_group;" ::: "memory")
#define CP_WAIT1()  asm volatile("cp.async.wait_group 1;" ::: "memory")

// ---------------------------------------------------------------------------
// W transpose: g_Wt[k][g] = W[g][k]
// ---------------------------------------------------------------------------
__global__ void wt_kernel(const float* __restrict__ W) {
    __shared__ float t[32][33];
    const int bx = blockIdx.x * 32, by = blockIdx.y * 32;
#pragma unroll
    for (int j = 0; j < 4; j++)
        t[threadIdx.y + 8 * j][threadIdx.x] =
            W[(size_t)(by + threadIdx.y + 8 * j) * Fn + bx + threadIdx.x];
    __syncthreads();
#pragma unroll
    for (int j = 0; j < 4; j++)
        g_Wt[(size_t)(bx + threadIdx.y + 8 * j) * Fn + by + threadIdx.x] =
            t[threadIdx.x][threadIdx.y + 8 * j];
}

__global__ void pad_kernel() {}   // launch-position padding so ncu captures the GEMM

// ---------------------------------------------------------------------------
// SGEMM:  C[M,512] = A[M,512] * W^T  via FFMA2, LDS-minimized microtile.
// CTA tile 128x128, 128 threads, microtile 8 rows x 16 cols (as 8 f32x2 pairs),
// BK=16. A: LDG->reg->STS transposed [k][row] (stride 132 = 528B: 16B-aligned
// rows, 2-way STS conflict only). B: cp.async from pre-transposed g_Wt,
// [k][col] layout, triple-buffered.
// Per thread per k: A 32B + B 64B = 96B for 128 lane-FMAs (was 64B/64).
// ---------------------------------------------------------------------------
__global__ __launch_bounds__(128, 2)
void sgemm_f32x2_kernel(const float* __restrict__ A)
{
    __shared__ __align__(16) float As[2][16][132];   // [buf][k][row]
    __shared__ __align__(16) float Bs[3][16][128];   // [buf][k][col]

    const int tid  = threadIdx.x;
    const int tx   = tid & 7;             // col chunks: tx*4 + 32c, c=0..3
    const int ty   = tid >> 3;            // rows ty*8 .. ty*8+7
    const int row0 = blockIdx.y * 128;
    const int col0 = blockIdx.x * 128;

    // A loader: thread covers rows {arow+32q}, k-quad akq (fixed)
    const int arow = tid >> 2;            // 0..31
    const int akq  = (tid & 3) * 4;       // 0,4,8,12
    const float* Ap = A + (size_t)row0 * Fn;

    // B loader: 512 16B-chunks, 4 per thread: f = q*128+tid -> k=f>>5, c16=(f&31)*4
    const uint32_t sbB = smem_to_u32(&Bs[0][0][0]);
    auto issueB = [&](int it, int buf) {
        const int kt = it * 16;
#pragma unroll
        for (int q = 0; q < 4; q++) {
            int f = q * 128 + tid;
            int k = f >> 5, c16 = (f & 31) * 4;
            const float* src = g_Wt + (size_t)(kt + k) * Fn + col0 + c16;
            uint32_t dst = sbB + (uint32_t)(buf * 16 * 128 + k * 128 + c16) * 4u;
            CP_ASYNC16(dst, src);
        }
    };

    float4 areg[4];
#pragma unroll
    for (int q = 0; q < 4; q++)
        areg[q] = *(const float4*)(Ap + (size_t)(arow + 32 * q) * Fn + akq);

    issueB(0, 0); CP_COMMIT();
    issueB(1, 1); CP_COMMIT();

    // stage A tile 0 into buffer 0
#pragma unroll
    for (int q = 0; q < 4; q++) {
        As[0][akq + 0][arow + 32 * q] = areg[q].x;
        As[0][akq + 1][arow + 32 * q] = areg[q].y;
        As[0][akq + 2][arow + 32 * q] = areg[q].z;
        As[0][akq + 3][arow + 32 * q] = areg[q].w;
    }

    uint64_t acc[8][8];                   // [row i][col-pair jp]; jp=2c+h
#pragma unroll
    for (int i = 0; i < 8; i++)
#pragma unroll
        for (int j = 0; j < 8; j++) acc[i][j] = 0ull;

    for (int it = 0; it < 32; ++it) {
        const int ab = it & 1;
        const int bb = it % 3;
        CP_WAIT1();                       // B(it) resident
        __syncthreads();                  // + A(it) staged by all

        if (it + 1 < 32) {                // prefetch next A tile into regs
            const int kt = (it + 1) * 16;
#pragma unroll
            for (int q = 0; q < 4; q++)
                areg[q] = *(const float4*)(Ap + (size_t)(arow + 32 * q) * Fn + kt + akq);
        }
        if (it + 2 < 32) { issueB(it + 2, (it + 2) % 3); }
        CP_COMMIT();

#pragma unroll
        for (int k = 0; k < 16; k++) {
            float4 a0 = *(const float4*)(&As[ab][k][ty * 8]);
            float4 a1 = *(const float4*)(&As[ab][k][ty * 8 + 4]);
            uint64_t bv[8];
#pragma unroll
            for (int c = 0; c < 4; c++) {
                ulonglong2 b2 = *(const ulonglong2*)(&Bs[bb][k][tx * 4 + 32 * c]);
                bv[2 * c]     = b2.x;
                bv[2 * c + 1] = b2.y;
            }
            uint64_t ad[8] = { dup2(a0.x), dup2(a0.y), dup2(a0.z), dup2(a0.w),
                               dup2(a1.x), dup2(a1.y), dup2(a1.z), dup2(a1.w) };
#pragma unroll
            for (int i = 0; i < 8; i++)
#pragma unroll
                for (int jp = 0; jp < 8; jp++)
                    ffma2(acc[i][jp], ad[i], bv[jp]);
        }

        if (it + 1 < 32) {                // stage next A into the other buffer
            const int nb = ab ^ 1;
#pragma unroll
            for (int q = 0; q < 4; q++) {
                As[nb][akq + 0][arow + 32 * q] = areg[q].x;
                As[nb][akq + 1][arow + 32 * q] = areg[q].y;
                As[nb][akq + 2][arow + 32 * q] = areg[q].z;
                As[nb][akq + 3][arow + 32 * q] = areg[q].w;
            }
        }
    }

    // epilogue: cols tx*4+32c (+0..3), 16B stores
#pragma unroll
    for (int i = 0; i < 8; i++) {
        float* rp = g_xs + (size_t)(row0 + ty * 8 + i) * Fn + col0;
#pragma unroll
        for (int c = 0; c < 4; c++) {
            ulonglong2 v = { acc[i][2 * c], acc[i][2 * c + 1] };
            *(ulonglong2*)(rp + tx * 4 + 32 * c) = v;
        }
    }
}

// ---------------------------------------------------------------------------
// LIF scan: one thread per neuron, sequential over T with 8-deep x prefetch.
// Matches reference arithmetic exactly.
// ---------------------------------------------------------------------------
__global__ __launch_bounds__(256)
void lif_scan_kernel(float* __restrict__ out)
{
    const int n = blockIdx.x * blockDim.x + threadIdx.x;   // 0..65535
    const float* xp = g_xs + n;

    float v = 0.0f, cur = 0.0f, z = 0.0f;

    float xb[8];
#pragma unroll
    for (int j = 0; j < 8; j++) xb[j] = __ldg(xp + (size_t)j * NEURONS);

    for (int t0 = 0; t0 < Tn; t0 += 8) {
        float xn[8] = {0.f, 0.f, 0.f, 0.f, 0.f, 0.f, 0.f, 0.f};
        if (t0 + 8 < Tn) {
#pragma unroll
            for (int j = 0; j < 8; j++)
                xn[j] = __ldg(xp + (size_t)(t0 + 8 + j) * NEURONS);
        }
#pragma unroll
        for (int j = 0; j < 8; j++) {
            float vd = fmaf(0.1f, cur - v, v);       // v + 0.1*((0-v)+i)
            float id = fmaf(-0.2f, cur, cur);        // i + (-0.2)*i
            bool  sp = (vd - 1.0f) > 0.0f;
            z   = sp ? 1.0f : 0.0f;
            v   = sp ? 0.0f : vd;
            cur = id + xb[j];
        }
#pragma unroll
        for (int j = 0; j < 8; j++) xb[j] = xn[j];
    }

    out[n]               = z;   // z_final
    out[NEURONS + n]     = z;   // z_final (returned twice)
    out[2 * NEURONS + n] = v;   // v_final
    out[3 * NEURONS + n] = cur; // i_final
}

// ---------------------------------------------------------------------------
extern "C" void kernel_launch(void* const* d_in, const int* in_sizes, int n_in,
                              void* d_out, int out_size)
{
    const float* spikes = (const float*)d_in[0];   // [1024,128,512]
    const float* W      = (const float*)d_in[1];   // [512,512]
    float* out          = (float*)d_out;           // 4 * 65536 floats

    // 5 launches before the GEMM -> ncu (-s 5 -c 1) profiles the GEMM kernel
    wt_kernel<<<dim3(16, 16), dim3(32, 8)>>>(W);
    pad_kernel<<<1, 1>>>();
    pad_kernel<<<1, 1>>>();
    pad_kernel<<<1, 1>>>();
    pad_kernel<<<1, 1>>>();

    dim3 grid(Fn / 128, Mrows / 128);              // (4, 1024)
    sgemm_f32x2_kernel<<<grid, 128>>>(spikes);
    lif_scan_kernel<<<NEURONS / 256, 256>>>(out);
}

// round 15
// speedup vs baseline: 2.2898x; 1.0169x over previous
#include <cuda_runtime.h>
#include <cstdint>

// Problem shape (fixed): T=1024, B=128, F=512
//   xs[t,b,g] = sum_f spikes[t,b,f] * W[g,f]   -> GEMM  M=131072, N=512, K=512
//   then sequential LIF scan over t, output final (z, z, v, i), each [128,512].

#define Tn 1024
#define Bn 128
#define Fn 512
#define Mrows (Tn * Bn)          // 131072
#define NEURONS (Bn * Fn)        // 65536

// module-scope device scratch (allowed; not a runtime alloc)
__device__ float g_xs[(size_t)Mrows * Fn];     // 268 MB
__device__ float g_Wt[Fn * Fn];                // W transposed: Wt[k][g]

// packed dual fp32 FMA: d.lo += a.lo*b.lo ; d.hi += a.hi*b.hi (IEEE fp32 each)
__device__ __forceinline__ void ffma2(uint64_t& d, uint64_t a, uint64_t b) {
    asm("fma.rn.f32x2 %0, %1, %2, %0;" : "+l"(d) : "l"(a), "l"(b));
}
__device__ __forceinline__ uint64_t dup2(float x) {
    uint64_t r;
    asm("mov.b64 %0, {%1, %1};" : "=l"(r) : "f"(x));
    return r;
}
__device__ __forceinline__ uint32_t smem_to_u32(const void* p) {
    uint32_t a;
    asm("{ .reg .u64 t; cvta.to.shared.u64 t, %1; cvt.u32.u64 %0, t; }"
        : "=r"(a) : "l"(p));
    return a;
}
#define CP_ASYNC16(dst, src) \
    asm volatile("cp.async.cg.shared.global [%0], [%1], 16;" \
        :: "r"(dst), "l"(src) : "memory")
#define CP_COMMIT() asm volatile("cp.async.commit_group;" ::: "memory")
#define CP_WAIT1()  asm volatile("cp.async.wait_group 1;" ::: "memory")

// ---------------------------------------------------------------------------
// W transpose: g_Wt[k][g] = W[g][k]
// ---------------------------------------------------------------------------
__global__ void wt_kernel(const float* __restrict__ W) {
    __shared__ float t[32][33];
    const int bx = blockIdx.x * 32, by = blockIdx.y * 32;
#pragma unroll
    for (int j = 0; j < 4; j++)
        t[threadIdx.y + 8 * j][threadIdx.x] =
            W[(size_t)(by + threadIdx.y + 8 * j) * Fn + bx + threadIdx.x];
    __syncthreads();
#pragma unroll
    for (int j = 0; j < 4; j++)
        g_Wt[(size_t)(bx + threadIdx.y + 8 * j) * Fn + by + threadIdx.x] =
            t[threadIdx.x][threadIdx.y + 8 * j];
}

// ---------------------------------------------------------------------------
// SGEMM:  C[M,512] = A[M,512] * W^T  via FFMA2.
// CTA tile 128x128, 128 threads, microtile 8 rows x 16 cols (8 f32x2 pairs),
// BK=32 (16 barriers total). A: LDG->reg->STS transposed [k][row], stride 132
// (16B-aligned rows), double-buffered. B: cp.async from pre-transposed g_Wt,
// [k][col], triple-buffered 32-k stages.
// ---------------------------------------------------------------------------
__global__ __launch_bounds__(128, 2)
void sgemm_f32x2_kernel(const float* __restrict__ A)
{
    __shared__ __align__(16) float As[2][32][132];   // [buf][k][row]
    __shared__ __align__(16) float Bs[3][32][128];   // [buf][k][col]

    const int tid  = threadIdx.x;
    const int tx   = tid & 7;             // col chunks: tx*4 + 32c, c=0..3
    const int ty   = tid >> 3;            // rows ty*8 .. ty*8+7
    const int row0 = blockIdx.y * 128;
    const int col0 = blockIdx.x * 128;

    // A loader: rows {arow+32q}, k-quads {akq, akq+16}
    const int arow = tid >> 2;            // 0..31
    const int akq  = (tid & 3) * 4;       // 0,4,8,12
    const float* Ap = A + (size_t)row0 * Fn;

    // B loader: 1024 16B-chunks per 32-k tile, 8 per thread
    const uint32_t sbB = smem_to_u32(&Bs[0][0][0]);
    auto issueB = [&](int it, int buf) {
        const int kt = it * 32;
#pragma unroll
        for (int q = 0; q < 8; q++) {
            int f = q * 128 + tid;
            int k = f >> 5, c16 = (f & 31) * 4;
            const float* src = g_Wt + (size_t)(kt + k) * Fn + col0 + c16;
            uint32_t dst = sbB + (uint32_t)(buf * 32 * 128 + k * 128 + c16) * 4u;
            CP_ASYNC16(dst, src);
        }
    };

    float4 areg[8];                       // [q][j]: rows arow+32q, k akq+16j
    auto loadAreg = [&](int it) {
        const int kt = it * 32;
#pragma unroll
        for (int q = 0; q < 4; q++) {
#pragma unroll
            for (int j = 0; j < 2; j++)
                areg[q * 2 + j] = *(const float4*)(Ap + (size_t)(arow + 32 * q) * Fn
                                                   + kt + akq + 16 * j);
        }
    };
    auto stsA = [&](int buf) {
#pragma unroll
        for (int q = 0; q < 4; q++) {
#pragma unroll
            for (int j = 0; j < 2; j++) {
                const int kk = akq + 16 * j;
                As[buf][kk + 0][arow + 32 * q] = areg[q * 2 + j].x;
                As[buf][kk + 1][arow + 32 * q] = areg[q * 2 + j].y;
                As[buf][kk + 2][arow + 32 * q] = areg[q * 2 + j].z;
                As[buf][kk + 3][arow + 32 * q] = areg[q * 2 + j].w;
            }
        }
    };

    issueB(0, 0); CP_COMMIT();
    loadAreg(0);
    issueB(1, 1); CP_COMMIT();
    stsA(0);

    uint64_t acc[8][8];                   // [row i][col-pair jp]; jp=2c+h
#pragma unroll
    for (int i = 0; i < 8; i++)
#pragma unroll
        for (int j = 0; j < 8; j++) acc[i][j] = 0ull;

    for (int it = 0; it < 16; ++it) {
        const int ab = it & 1;
        const int bb = it % 3;
        CP_WAIT1();                       // B(it) resident
        __syncthreads();                  // + A(it) staged by all

        if (it + 1 < 16) loadAreg(it + 1);
        if (it + 2 < 16) issueB(it + 2, (it + 2) % 3);
        CP_COMMIT();

#pragma unroll
        for (int k = 0; k < 32; k++) {
            float4 a0 = *(const float4*)(&As[ab][k][ty * 8]);
            float4 a1 = *(const float4*)(&As[ab][k][ty * 8 + 4]);
            uint64_t bv[8];
#pragma unroll
            for (int c = 0; c < 4; c++) {
                ulonglong2 b2 = *(const ulonglong2*)(&Bs[bb][k][tx * 4 + 32 * c]);
                bv[2 * c]     = b2.x;
                bv[2 * c + 1] = b2.y;
            }
            uint64_t ad[8] = { dup2(a0.x), dup2(a0.y), dup2(a0.z), dup2(a0.w),
                               dup2(a1.x), dup2(a1.y), dup2(a1.z), dup2(a1.w) };
#pragma unroll
            for (int i = 0; i < 8; i++)
#pragma unroll
                for (int jp = 0; jp < 8; jp++)
                    ffma2(acc[i][jp], ad[i], bv[jp]);
        }

        if (it + 1 < 16) stsA(ab ^ 1);
    }

    // epilogue: cols tx*4+32c (+0..3), 16B stores
#pragma unroll
    for (int i = 0; i < 8; i++) {
        float* rp = g_xs + (size_t)(row0 + ty * 8 + i) * Fn + col0;
#pragma unroll
        for (int c = 0; c < 4; c++) {
            ulonglong2 v = { acc[i][2 * c], acc[i][2 * c + 1] };
            *(ulonglong2*)(rp + tx * 4 + 32 * c) = v;
        }
    }
}

// ---------------------------------------------------------------------------
// LIF scan: one thread per neuron, sequential over T with 8-deep x prefetch.
// Matches reference arithmetic exactly.
// ---------------------------------------------------------------------------
__global__ __launch_bounds__(256)
void lif_scan_kernel(float* __restrict__ out)
{
    const int n = blockIdx.x * blockDim.x + threadIdx.x;   // 0..65535
    const float* xp = g_xs + n;

    float v = 0.0f, cur = 0.0f, z = 0.0f;

    float xb[8];
#pragma unroll
    for (int j = 0; j < 8; j++) xb[j] = __ldg(xp + (size_t)j * NEURONS);

    for (int t0 = 0; t0 < Tn; t0 += 8) {
        float xn[8] = {0.f, 0.f, 0.f, 0.f, 0.f, 0.f, 0.f, 0.f};
        if (t0 + 8 < Tn) {
#pragma unroll
            for (int j = 0; j < 8; j++)
                xn[j] = __ldg(xp + (size_t)(t0 + 8 + j) * NEURONS);
        }
#pragma unroll
        for (int j = 0; j < 8; j++) {
            float vd = fmaf(0.1f, cur - v, v);       // v + 0.1*((0-v)+i)
            float id = fmaf(-0.2f, cur, cur);        // i + (-0.2)*i
            bool  sp = (vd - 1.0f) > 0.0f;
            z   = sp ? 1.0f : 0.0f;
            v   = sp ? 0.0f : vd;
            cur = id + xb[j];
        }
#pragma unroll
        for (int j = 0; j < 8; j++) xb[j] = xn[j];
    }

    out[n]               = z;   // z_final
    out[NEURONS + n]     = z;   // z_final (returned twice)
    out[2 * NEURONS + n] = v;   // v_final
    out[3 * NEURONS + n] = cur; // i_final
}

// ---------------------------------------------------------------------------
extern "C" void kernel_launch(void* const* d_in, const int* in_sizes, int n_in,
                              void* d_out, int out_size)
{
    const float* spikes = (const float*)d_in[0];   // [1024,128,512]
    const float* W      = (const float*)d_in[1];   // [512,512]
    float* out          = (float*)d_out;           // 4 * 65536 floats

    wt_kernel<<<dim3(16, 16), dim3(32, 8)>>>(W);
    dim3 grid(Fn / 128, Mrows / 128);              // (4, 1024)
    sgemm_f32x2_kernel<<<grid, 128>>>(spikes);
    lif_scan_kernel<<<NEURONS / 256, 256>>>(out);
}